// round 1
// baseline (speedup 1.0000x reference)
#include <cuda_runtime.h>
#include <cuda_bf16.h>
#include <cstdint>

// Problem dims
#define M_DIM 4096           // batch
#define N_DIM 1024           // out_dim
#define E_DIM 16             // experts
#define I_DIM 1024           // in_dim
#define K_DIM (E_DIM * I_DIM) // 16384 reduction

// GEMM tiling
#define BM 128
#define BN 128
#define BK 32
#define STAGES 3
#define NTHREADS 256

// Per-stage smem layout (bytes)
#define A_HI_OFF 0
#define A_LO_OFF 8192
#define B_HI_OFF 16384
#define B_LO_OFF 24576
#define STAGE_BYTES 32768

// ---------------- scratch (device globals; no runtime allocation) ----------
__device__ __nv_bfloat16 g_Ahi[(size_t)M_DIM * K_DIM];  // 128 MiB
__device__ __nv_bfloat16 g_Alo[(size_t)M_DIM * K_DIM];  // 128 MiB
__device__ __nv_bfloat16 g_Whi[(size_t)K_DIM * N_DIM];  // 32 MiB
__device__ __nv_bfloat16 g_Wlo[(size_t)K_DIM * N_DIM];  // 32 MiB
__device__ float         g_C0 [(size_t)M_DIM * N_DIM];  // 16 MiB  (cw @ bias)

// ---------------- prep kernels ---------------------------------------------
__global__ void prep_w_kernel(const float* __restrict__ W) {
    size_t idx    = (size_t)blockIdx.x * blockDim.x + threadIdx.x;
    size_t stride = (size_t)gridDim.x * blockDim.x;
    const size_t total = (size_t)K_DIM * N_DIM;
    for (; idx < total; idx += stride) {
        float w = W[idx];
        __nv_bfloat16 hi = __float2bfloat16(w);
        float rem = w - __bfloat162float(hi);
        g_Whi[idx] = hi;
        g_Wlo[idx] = __float2bfloat16(rem);
    }
}

__global__ void prep_a_kernel(const float* __restrict__ x,
                              const float* __restrict__ cw) {
    size_t idx    = (size_t)blockIdx.x * blockDim.x + threadIdx.x;
    size_t stride = (size_t)gridDim.x * blockDim.x;
    const size_t total = (size_t)M_DIM * K_DIM;
    for (; idx < total; idx += stride) {
        size_t b = idx >> 14;           // / 16384
        int    k = (int)(idx & 16383);
        int    n = k >> 10;
        int    i = k & 1023;
        float v = cw[b * E_DIM + n] * x[(b << 10) + i];
        __nv_bfloat16 hi = __float2bfloat16(v);
        float rem = v - __bfloat162float(hi);
        g_Ahi[idx] = hi;
        g_Alo[idx] = __float2bfloat16(rem);
    }
}

__global__ void prep_c0_kernel(const float* __restrict__ cw,
                               const float* __restrict__ bias) {
    size_t idx = (size_t)blockIdx.x * blockDim.x + threadIdx.x;
    if (idx >= (size_t)M_DIM * N_DIM) return;
    size_t b = idx >> 10;
    int    o = (int)(idx & 1023);
    float s = 0.f;
#pragma unroll
    for (int n = 0; n < E_DIM; ++n)
        s += cw[b * E_DIM + n] * bias[n * N_DIM + o];
    g_C0[idx] = s;
}

// ---------------- asm helpers ----------------------------------------------
__device__ __forceinline__ void cp_async16(uint32_t s, const void* g) {
    asm volatile("cp.async.cg.shared.global [%0], [%1], 16;\n" :: "r"(s), "l"(g));
}
__device__ __forceinline__ void cp_commit() {
    asm volatile("cp.async.commit_group;\n" ::: "memory");
}
template <int N>
__device__ __forceinline__ void cp_wait() {
    asm volatile("cp.async.wait_group %0;\n" :: "n"(N) : "memory");
}
__device__ __forceinline__ void ldsm_x4(uint32_t* r, uint32_t addr) {
    asm volatile("ldmatrix.sync.aligned.m8n8.x4.shared.b16 {%0,%1,%2,%3}, [%4];"
                 : "=r"(r[0]), "=r"(r[1]), "=r"(r[2]), "=r"(r[3]) : "r"(addr));
}
__device__ __forceinline__ void ldsm_x4_t(uint32_t* r, uint32_t addr) {
    asm volatile("ldmatrix.sync.aligned.m8n8.x4.trans.shared.b16 {%0,%1,%2,%3}, [%4];"
                 : "=r"(r[0]), "=r"(r[1]), "=r"(r[2]), "=r"(r[3]) : "r"(addr));
}
__device__ __forceinline__ void mma_bf16(float* c, const uint32_t* a, const uint32_t* b) {
    asm volatile(
        "mma.sync.aligned.m16n8k16.row.col.f32.bf16.bf16.f32 "
        "{%0,%1,%2,%3}, {%4,%5,%6,%7}, {%8,%9}, {%0,%1,%2,%3};"
        : "+f"(c[0]), "+f"(c[1]), "+f"(c[2]), "+f"(c[3])
        : "r"(a[0]), "r"(a[1]), "r"(a[2]), "r"(a[3]), "r"(b[0]), "r"(b[1]));
}

// ---------------- tile loader ----------------------------------------------
// A tile: [128 rows][32 k] bf16, row = 64B = 4 x 16B chunks, swizzle: ch ^ ((row>>1)&3)
// B tile: [32 k-rows][128 n] bf16, row = 256B = 16 chunks,   swizzle: ch ^ (r&7)
__device__ __forceinline__ void issue_stage(uint32_t st,
                                            const __nv_bfloat16* __restrict__ Ahi_g,
                                            const __nv_bfloat16* __restrict__ Alo_g,
                                            const __nv_bfloat16* __restrict__ Bhi_g,
                                            const __nv_bfloat16* __restrict__ Blo_g,
                                            int kt, int tid) {
    const int k0 = kt * BK;
#pragma unroll
    for (int p = 0; p < 2; ++p) {           // A: 512 chunks / 256 threads
        int c   = tid + p * 256;
        int row = c >> 2;
        int ch  = c & 3;
        uint32_t soff = (uint32_t)(row * 64 + ((ch ^ ((row >> 1) & 3)) << 4));
        size_t   goff = (size_t)row * K_DIM + k0 + ch * 8;
        cp_async16(st + A_HI_OFF + soff, Ahi_g + goff);
        cp_async16(st + A_LO_OFF + soff, Alo_g + goff);
    }
#pragma unroll
    for (int p = 0; p < 2; ++p) {           // B: 512 chunks / 256 threads
        int c  = tid + p * 256;
        int r  = c >> 4;
        int ch = c & 15;
        uint32_t soff = (uint32_t)(r * 256 + ((ch ^ (r & 7)) << 4));
        size_t   goff = (size_t)(k0 + r) * N_DIM + ch * 8;
        cp_async16(st + B_HI_OFF + soff, Bhi_g + goff);
        cp_async16(st + B_LO_OFF + soff, Blo_g + goff);
    }
}

// ---------------- main GEMM -------------------------------------------------
// C = Ahi@Whi + Ahi@Wlo + Alo@Whi (fp32 accum), epilogue adds C0 and applies ReLU.
__global__ void __launch_bounds__(NTHREADS, 1)
gemm_kernel(float* __restrict__ out) {
    extern __shared__ char smem_raw[];
    const uint32_t smem_base = (uint32_t)__cvta_generic_to_shared(smem_raw);
    const int tid  = threadIdx.x;
    const int lane = tid & 31;
    const int warp = tid >> 5;
    const int wm   = warp >> 2;   // 0..1
    const int wn   = warp & 3;    // 0..3
    const int bm0  = blockIdx.y * BM;
    const int bn0  = blockIdx.x * BN;

    const __nv_bfloat16* Ahi_g = g_Ahi + (size_t)bm0 * K_DIM;
    const __nv_bfloat16* Alo_g = g_Alo + (size_t)bm0 * K_DIM;
    const __nv_bfloat16* Bhi_g = g_Whi + bn0;
    const __nv_bfloat16* Blo_g = g_Wlo + bn0;

    float c[4][4][4];
#pragma unroll
    for (int i = 0; i < 4; ++i)
#pragma unroll
        for (int j = 0; j < 4; ++j)
#pragma unroll
            for (int k = 0; k < 4; ++k) c[i][j][k] = 0.f;

    const int KT = K_DIM / BK; // 512

#pragma unroll
    for (int s = 0; s < STAGES - 1; ++s) {
        issue_stage(smem_base + s * STAGE_BYTES, Ahi_g, Alo_g, Bhi_g, Blo_g, s, tid);
        cp_commit();
    }

    const int a_row16 = lane & 15;
    const int hi_half = lane >> 4;

    int buf = 0;
    for (int kt = 0; kt < KT; ++kt) {
        cp_wait<STAGES - 2>();
        __syncthreads();

        const int load_kt = kt + STAGES - 1;
        int load_buf = buf + (STAGES - 1);
        if (load_buf >= STAGES) load_buf -= STAGES;
        if (load_kt < KT)
            issue_stage(smem_base + load_buf * STAGE_BYTES, Ahi_g, Alo_g, Bhi_g, Blo_g, load_kt, tid);
        cp_commit();

        const uint32_t st = smem_base + buf * STAGE_BYTES;
#pragma unroll
        for (int s = 0; s < 2; ++s) {       // two k16 steps per BK=32
            uint32_t ahi[4][4], alo[4][4];
#pragma unroll
            for (int mt = 0; mt < 4; ++mt) {
                int row = wm * 64 + mt * 16 + a_row16;
                int ch  = s * 2 + hi_half;
                uint32_t off = (uint32_t)(row * 64 + ((ch ^ ((row >> 1) & 3)) << 4));
                ldsm_x4(ahi[mt], st + A_HI_OFF + off);
                ldsm_x4(alo[mt], st + A_LO_OFF + off);
            }
            uint32_t bhi[4][2], blo[4][2];
#pragma unroll
            for (int nt2 = 0; nt2 < 2; ++nt2) {
                int r  = s * 16 + (lane & 15);
                int ch = wn * 4 + nt2 * 2 + hi_half;
                uint32_t off = (uint32_t)(r * 256 + ((ch ^ (r & 7)) << 4));
                uint32_t t[4];
                ldsm_x4_t(t, st + B_HI_OFF + off);
                bhi[nt2 * 2][0] = t[0]; bhi[nt2 * 2][1] = t[1];
                bhi[nt2 * 2 + 1][0] = t[2]; bhi[nt2 * 2 + 1][1] = t[3];
                ldsm_x4_t(t, st + B_LO_OFF + off);
                blo[nt2 * 2][0] = t[0]; blo[nt2 * 2][1] = t[1];
                blo[nt2 * 2 + 1][0] = t[2]; blo[nt2 * 2 + 1][1] = t[3];
            }
#pragma unroll
            for (int mt = 0; mt < 4; ++mt)
#pragma unroll
                for (int nt = 0; nt < 4; ++nt) {
                    mma_bf16(c[mt][nt], ahi[mt], bhi[nt]);
                    mma_bf16(c[mt][nt], ahi[mt], blo[nt]);
                    mma_bf16(c[mt][nt], alo[mt], bhi[nt]);
                }
        }
        buf = (buf + 1 == STAGES) ? 0 : buf + 1;
    }

    // epilogue: add cw@bias term, ReLU, store fp32
    const int gr = lane >> 2;
    const int ct = lane & 3;
#pragma unroll
    for (int mt = 0; mt < 4; ++mt) {
#pragma unroll
        for (int nt = 0; nt < 4; ++nt) {
            int brow = bm0 + wm * 64 + mt * 16 + gr;
            int o    = bn0 + wn * 32 + nt * 8 + ct * 2;
            size_t i0 = (size_t)brow * N_DIM + o;
            out[i0]     = fmaxf(c[mt][nt][0] + g_C0[i0], 0.f);
            out[i0 + 1] = fmaxf(c[mt][nt][1] + g_C0[i0 + 1], 0.f);
            size_t i1 = i0 + (size_t)8 * N_DIM;
            out[i1]     = fmaxf(c[mt][nt][2] + g_C0[i1], 0.f);
            out[i1 + 1] = fmaxf(c[mt][nt][3] + g_C0[i1 + 1], 0.f);
        }
    }
}

// ---------------- launch -----------------------------------------------------
extern "C" void kernel_launch(void* const* d_in, const int* in_sizes, int n_in,
                              void* d_out, int out_size) {
    const float* x = nullptr;
    const float* cw = nullptr;
    const float* W = nullptr;
    const float* bias = nullptr;
    for (int i = 0; i < n_in; ++i) {
        switch (in_sizes[i]) {
            case M_DIM * I_DIM:          x    = (const float*)d_in[i]; break; // 4194304
            case M_DIM * E_DIM:          cw   = (const float*)d_in[i]; break; // 65536
            case E_DIM * I_DIM * N_DIM:  W    = (const float*)d_in[i]; break; // 16777216
            case E_DIM * N_DIM:          bias = (const float*)d_in[i]; break; // 16384
            default: break;
        }
    }
    float* out = (float*)d_out;

    prep_w_kernel<<<4096, 256>>>(W);
    prep_a_kernel<<<8192, 256>>>(x, cw);
    prep_c0_kernel<<<(M_DIM * N_DIM) / 256, 256>>>(cw, bias);

    cudaFuncSetAttribute(gemm_kernel, cudaFuncAttributeMaxDynamicSharedMemorySize,
                         STAGES * STAGE_BYTES);
    dim3 grid(N_DIM / BN, M_DIM / BM);  // x-fastest over N -> A-slab L2 reuse
    gemm_kernel<<<grid, NTHREADS, STAGES * STAGE_BYTES>>>(out);
}

// round 3
// speedup vs baseline: 2.9465x; 2.9465x over previous
#include <cuda_runtime.h>
#include <cuda_fp16.h>
#include <cstdint>

// ---------------- problem dims ----------------
#define M_DIM 4096
#define N_DIM 1024
#define E_DIM 16
#define I_DIM 1024
#define K_DIM 16384

// ---------------- GEMM config -----------------
#define BM 128
#define BN 128
#define BK 64
#define STAGES 3
#define NTHREADS 256

// per-stage smem (bytes): A[128][64] fp16 (16KB) + B[64][128] fp16 (16KB)
#define A_OFF 0
#define B_OFF 16384
#define STAGE_BYTES 32768

// ---------------- device scratch --------------
__device__ __align__(1024) __half g_A[(size_t)M_DIM * K_DIM];   // 128 MiB: cw*x in fp16
__device__ __align__(1024) __half g_W[(size_t)K_DIM * N_DIM];   // 32 MiB:  W in fp16 (same [k][o] layout)
__device__ __align__(1024) float  g_C0[(size_t)M_DIM * N_DIM];  // 16 MiB:  cw @ bias

// ---------------- prep kernels ----------------
__global__ void prep_w_kernel(const float* __restrict__ W) {
    size_t idx    = (size_t)blockIdx.x * blockDim.x + threadIdx.x;
    size_t stride = (size_t)gridDim.x * blockDim.x;
    const size_t total4 = (size_t)K_DIM * N_DIM / 4;
    for (; idx < total4; idx += stride) {
        float4 w = *reinterpret_cast<const float4*>(W + idx * 4);
        __half2 h01 = __floats2half2_rn(w.x, w.y);
        __half2 h23 = __floats2half2_rn(w.z, w.w);
        *reinterpret_cast<__half2*>(g_W + idx * 4)     = h01;
        *reinterpret_cast<__half2*>(g_W + idx * 4 + 2) = h23;
    }
}

// A[b][k] = fp16( cw[b][k>>10] * x[b][k&1023] )
__global__ void prep_a_kernel(const float* __restrict__ x,
                              const float* __restrict__ cw) {
    size_t idx    = (size_t)blockIdx.x * blockDim.x + threadIdx.x;
    size_t stride = (size_t)gridDim.x * blockDim.x;
    const size_t total4 = (size_t)M_DIM * K_DIM / 4;
    for (; idx < total4; idx += stride) {
        size_t base = idx * 4;
        size_t b = base >> 14;
        int    k = (int)(base & 16383);
        int    e = k >> 10;
        int    i = k & 1023;
        float c = cw[b * E_DIM + e];
        float4 xv = *reinterpret_cast<const float4*>(x + (b << 10) + i);
        __half2 h01 = __floats2half2_rn(c * xv.x, c * xv.y);
        __half2 h23 = __floats2half2_rn(c * xv.z, c * xv.w);
        *reinterpret_cast<__half2*>(g_A + base)     = h01;
        *reinterpret_cast<__half2*>(g_A + base + 2) = h23;
    }
}

__global__ void prep_c0_kernel(const float* __restrict__ cw,
                               const float* __restrict__ bias) {
    size_t idx = (size_t)blockIdx.x * blockDim.x + threadIdx.x;
    if (idx >= (size_t)M_DIM * N_DIM) return;
    size_t b = idx >> 10;
    int    o = (int)(idx & 1023);
    float s = 0.f;
#pragma unroll
    for (int n = 0; n < E_DIM; ++n)
        s += cw[b * E_DIM + n] * bias[n * N_DIM + o];
    g_C0[idx] = s;
}

// ---------------- asm helpers ----------------
__device__ __forceinline__ void cp_async16(uint32_t s, const void* g) {
    asm volatile("cp.async.cg.shared.global [%0], [%1], 16;\n" :: "r"(s), "l"(g));
}
__device__ __forceinline__ void cp_commit() {
    asm volatile("cp.async.commit_group;\n" ::: "memory");
}
template <int N>
__device__ __forceinline__ void cp_wait() {
    asm volatile("cp.async.wait_group %0;\n" :: "n"(N) : "memory");
}
__device__ __forceinline__ void ldsm_x4(uint32_t* r, uint32_t addr) {
    asm volatile("ldmatrix.sync.aligned.m8n8.x4.shared.b16 {%0,%1,%2,%3}, [%4];"
                 : "=r"(r[0]), "=r"(r[1]), "=r"(r[2]), "=r"(r[3]) : "r"(addr));
}
__device__ __forceinline__ void ldsm_x4_t(uint32_t* r, uint32_t addr) {
    asm volatile("ldmatrix.sync.aligned.m8n8.x4.trans.shared.b16 {%0,%1,%2,%3}, [%4];"
                 : "=r"(r[0]), "=r"(r[1]), "=r"(r[2]), "=r"(r[3]) : "r"(addr));
}
__device__ __forceinline__ void mma_f16(float* c, const uint32_t* a, const uint32_t* b) {
    asm volatile(
        "mma.sync.aligned.m16n8k16.row.col.f32.f16.f16.f32 "
        "{%0,%1,%2,%3}, {%4,%5,%6,%7}, {%8,%9}, {%0,%1,%2,%3};"
        : "+f"(c[0]), "+f"(c[1]), "+f"(c[2]), "+f"(c[3])
        : "r"(a[0]), "r"(a[1]), "r"(a[2]), "r"(a[3]), "r"(b[0]), "r"(b[1]));
}

// ---------------- tile loader ----------------
// A tile: [128 rows][64 k] fp16, row = 128B = 8 x 16B chunks, swizzle: ch ^ (row & 7)
// B tile: [64 k-rows][128 n] fp16, row = 256B = 16 chunks,    swizzle: ch ^ (r & 7)
// Each thread: 4 A chunks + 4 B chunks per stage.
__device__ __forceinline__ void issue_stage(uint32_t st,
                                            const __half* pA, const __half* pB,
                                            uint32_t dstA0, uint32_t dstB0) {
#pragma unroll
    for (int p = 0; p < 4; ++p)
        cp_async16(st + A_OFF + dstA0 + p * (32 * 128),
                   pA + (size_t)p * 32 * K_DIM);
#pragma unroll
    for (int p = 0; p < 4; ++p)
        cp_async16(st + B_OFF + dstB0 + p * (16 * 256),
                   pB + (size_t)p * 16 * N_DIM);
}

// ---------------- main GEMM (fp16 single-pass HMMA) --------------------------
__global__ void __launch_bounds__(NTHREADS, 2)
gemm_kernel(float* __restrict__ out) {
    extern __shared__ char smem_raw[];
    const uint32_t smem_base = (uint32_t)__cvta_generic_to_shared(smem_raw);
    const int tid  = threadIdx.x;
    const int lane = tid & 31;
    const int warp = tid >> 5;
    const int wm   = warp >> 2;   // 0..1
    const int wn   = warp & 3;    // 0..3
    const int bm0  = blockIdx.y * BM;
    const int bn0  = blockIdx.x * BN;

    // producer state: fixed swizzled dst offsets + running global pointers
    const int arow = tid >> 3, ach = tid & 7;
    const int brow = tid >> 4, bch = tid & 15;
    const uint32_t dstA0 = (uint32_t)(arow * 128 + ((ach ^ (arow & 7)) << 4));
    const uint32_t dstB0 = (uint32_t)(brow * 256 + ((bch ^ (brow & 7)) << 4));
    const __half* pA = g_A + (size_t)(bm0 + arow) * K_DIM + ach * 8;
    const __half* pB = g_W + (size_t)brow * N_DIM + bn0 + bch * 8;

    float c[4][4][4];
#pragma unroll
    for (int i = 0; i < 4; ++i)
#pragma unroll
        for (int j = 0; j < 4; ++j)
#pragma unroll
            for (int k = 0; k < 4; ++k) c[i][j][k] = 0.f;

    const int KT = K_DIM / BK;  // 256

#pragma unroll
    for (int s = 0; s < STAGES - 1; ++s) {
        issue_stage(smem_base + s * STAGE_BYTES, pA, pB, dstA0, dstB0);
        pA += BK; pB += (size_t)BK * N_DIM;
        cp_commit();
    }

    const int a_row16  = lane & 15;
    const int hi_half  = lane >> 4;

    int buf = 0;
    for (int kt = 0; kt < KT; ++kt) {
        cp_wait<STAGES - 2>();
        __syncthreads();

        int load_buf = buf + (STAGES - 1);
        if (load_buf >= STAGES) load_buf -= STAGES;
        if (kt + STAGES - 1 < KT) {
            issue_stage(smem_base + load_buf * STAGE_BYTES, pA, pB, dstA0, dstB0);
            pA += BK; pB += (size_t)BK * N_DIM;
        }
        cp_commit();

        const uint32_t st = smem_base + buf * STAGE_BYTES;
#pragma unroll
        for (int s = 0; s < 4; ++s) {       // four k16 steps per BK=64
            uint32_t a[4][4];
#pragma unroll
            for (int mt = 0; mt < 4; ++mt) {
                int row = wm * 64 + mt * 16 + a_row16;
                int ch  = s * 2 + hi_half;
                uint32_t off = (uint32_t)(row * 128 + ((ch ^ (row & 7)) << 4));
                ldsm_x4(a[mt], st + A_OFF + off);
            }
            uint32_t b[4][2];
#pragma unroll
            for (int nt2 = 0; nt2 < 2; ++nt2) {
                int r  = s * 16 + (lane & 15);
                int ch = wn * 4 + nt2 * 2 + hi_half;
                uint32_t off = (uint32_t)(r * 256 + ((ch ^ (r & 7)) << 4));
                uint32_t t[4];
                ldsm_x4_t(t, st + B_OFF + off);
                b[nt2 * 2][0] = t[0];     b[nt2 * 2][1] = t[1];
                b[nt2 * 2 + 1][0] = t[2]; b[nt2 * 2 + 1][1] = t[3];
            }
#pragma unroll
            for (int mt = 0; mt < 4; ++mt)
#pragma unroll
                for (int nt = 0; nt < 4; ++nt)
                    mma_f16(c[mt][nt], a[mt], b[nt]);
        }
        buf = (buf + 1 == STAGES) ? 0 : buf + 1;
    }

    // epilogue: add cw@bias term, ReLU, store fp32
    const int gr = lane >> 2;
    const int ct = lane & 3;
#pragma unroll
    for (int mt = 0; mt < 4; ++mt) {
#pragma unroll
        for (int nt = 0; nt < 4; ++nt) {
            int row = bm0 + wm * 64 + mt * 16 + gr;
            int o   = bn0 + wn * 32 + nt * 8 + ct * 2;
            size_t i0 = (size_t)row * N_DIM + o;
            out[i0]     = fmaxf(c[mt][nt][0] + g_C0[i0], 0.f);
            out[i0 + 1] = fmaxf(c[mt][nt][1] + g_C0[i0 + 1], 0.f);
            size_t i1 = i0 + (size_t)8 * N_DIM;
            out[i1]     = fmaxf(c[mt][nt][2] + g_C0[i1], 0.f);
            out[i1 + 1] = fmaxf(c[mt][nt][3] + g_C0[i1 + 1], 0.f);
        }
    }
}

// ---------------- launch -----------------------------------------------------
extern "C" void kernel_launch(void* const* d_in, const int* in_sizes, int n_in,
                              void* d_out, int out_size) {
    const float* x = nullptr;
    const float* cw = nullptr;
    const float* W = nullptr;
    const float* bias = nullptr;
    for (int i = 0; i < n_in; ++i) {
        switch (in_sizes[i]) {
            case M_DIM * I_DIM:         x    = (const float*)d_in[i]; break; // 4194304
            case M_DIM * E_DIM:         cw   = (const float*)d_in[i]; break; // 65536
            case E_DIM * I_DIM * N_DIM: W    = (const float*)d_in[i]; break; // 16777216
            case E_DIM * N_DIM:         bias = (const float*)d_in[i]; break; // 16384
            default: break;
        }
    }
    float* out = (float*)d_out;

    prep_w_kernel<<<2048, 256>>>(W);
    prep_a_kernel<<<8192, 256>>>(x, cw);
    prep_c0_kernel<<<(M_DIM * N_DIM + 255) / 256, 256>>>(cw, bias);

    cudaFuncSetAttribute(gemm_kernel, cudaFuncAttributeMaxDynamicSharedMemorySize,
                         STAGES * STAGE_BYTES);
    dim3 grid(N_DIM / BN, M_DIM / BM);  // (8, 32) = 256 CTAs
    gemm_kernel<<<grid, NTHREADS, STAGES * STAGE_BYTES>>>(out);
}